// round 17
// baseline (speedup 1.0000x reference)
#include <cuda_runtime.h>

// PointTransformerLayer  B=1, N=1024, D=64, H_POS=64, H_ATTN=256
//
// Round 9: LDS-wavefront reduction over Round-8 design.
//  - aW1 repacked in smem (pair-split) so GEMM1 weight LDS.64 are conflict-free
//  - float4 operand broadcasts (u, ph) with d/h step 4
// Everything else identical: one CTA per query i, 8 warps, each warp owns 8
// j-rows end-to-end, no CTA barriers in the tile loop, all GEMMs on fma.rn.f32x2.

#define NTOK 1024
#define DIM 64
#define TJ 64
#define RPW 8      // rows per warp per tile
#define HS 132     // Hbuf row stride in floats (128 cols + 4 pad)

// smem float offsets
#define OFF_AW1 0        // 64*256 (pair-split repacked)
#define OFF_AW2 16384    // 256*64
#define OFF_PW2 32768    // 64*64
#define OFF_HB  36864    // 64*HS = 8448  (PH aliases first 64 cols of each row)
#define OFF_U   45312    // 64*64
#define OFF_QI  49408    // 64
#define OFF_AIB 49472    // 64  (a_i + pb1)
#define OFF_AB1 49536    // 256
#define OFF_AB2 49792    // 64
#define OFF_PB2 49856    // 64
#define OFF_RED 49920    // 3*8*64
#define SMEM_FLOATS 51456
#define SMEM_BYTES (SMEM_FLOATS * 4)

__device__ float g_q[NTOK * DIM];
__device__ float g_k[NTOK * DIM];
__device__ float g_v[NTOK * DIM];
__device__ float g_a[NTOK * DIM];

typedef unsigned long long u64;

__device__ __forceinline__ u64 bcast2(float a) {
    u64 r; asm("mov.b64 %0, {%1,%1};" : "=l"(r) : "f"(a)); return r;
}
__device__ __forceinline__ void fma2(u64 &d, u64 a, u64 b) {
    asm("fma.rn.f32x2 %0, %1, %2, %0;" : "+l"(d) : "l"(a), "l"(b));
}
__device__ __forceinline__ float2 unpack2(u64 v) {
    float lo, hi;
    asm("mov.b64 {%0,%1}, %2;" : "=f"(lo), "=f"(hi) : "l"(v));
    return make_float2(lo, hi);
}

__global__ void proj_kernel(const float* __restrict__ x, const float* __restrict__ pos,
                            const float* __restrict__ Wq, const float* __restrict__ Wk,
                            const float* __restrict__ Wv, const float* __restrict__ pW1) {
    int i = blockIdx.x;
    int d = threadIdx.x;
    __shared__ float sx[DIM];
    sx[d] = x[i * DIM + d];
    __syncthreads();
    float q = 0.f, k = 0.f, v = 0.f;
#pragma unroll 8
    for (int e = 0; e < DIM; e++) {
        float xv = sx[e];
        q = fmaf(xv, Wq[e * DIM + d], q);
        k = fmaf(xv, Wk[e * DIM + d], k);
        v = fmaf(xv, Wv[e * DIM + d], v);
    }
    g_q[i * DIM + d] = q;
    g_k[i * DIM + d] = k;
    g_v[i * DIM + d] = v;
    float p0 = pos[i * 2 + 0], p1 = pos[i * 2 + 1];
    g_a[i * DIM + d] = p0 * pW1[d] + p1 * pW1[DIM + d];
}

__global__ void __launch_bounds__(256, 1)
pt_main(const float* __restrict__ pb1, const float* __restrict__ pW2,
        const float* __restrict__ pb2, const float* __restrict__ aW1,
        const float* __restrict__ ab1, const float* __restrict__ aW2,
        const float* __restrict__ ab2, float* __restrict__ out) {
    extern __shared__ float sm[];
    const int i = blockIdx.x;
    const int t = threadIdx.x;
    const int warp = t >> 5, lane = t & 31;
    const int rw = warp * RPW;

    // ---- cooperative loads ----
    {
        // aW1: pair-split repack. For (d, col): g=col>>7, r=col&127,
        // ln=r>>2, q=r&3 -> dst = d*256 + g*128 + (q>>1)*64 + 2*ln + (q&1).
        // GEMM1 lane ln then reads cols {g*128+4ln..+3} as two conflict-free
        // LDS.64 at (d*256 + g*128 + 2*ln) and (+64).
        for (int idx = t; idx < 16384; idx += 256) {
            int d = idx >> 8, col = idx & 255;
            int g = col >> 7, r = col & 127;
            int ln = r >> 2, q = r & 3;
            sm[OFF_AW1 + d * 256 + g * 128 + (q >> 1) * 64 + 2 * ln + (q & 1)] = aW1[idx];
        }
        const float4* s2 = (const float4*)aW2;
        float4* d2 = (float4*)(sm + OFF_AW2);
        for (int idx = t; idx < 4096; idx += 256) d2[idx] = s2[idx];
        const float4* s3 = (const float4*)pW2;
        float4* d3 = (float4*)(sm + OFF_PW2);
        for (int idx = t; idx < 1024; idx += 256) d3[idx] = s3[idx];
        // ab1 pair-split to match repacked aW1 column assignment
        {
            int col = t;
            int g = col >> 7, r = col & 127;
            int ln = r >> 2, q = r & 3;
            sm[OFF_AB1 + g * 128 + (q >> 1) * 64 + 2 * ln + (q & 1)] = ab1[col];
        }
        if (t < 64) {
            sm[OFF_QI + t] = g_q[i * DIM + t];
            sm[OFF_AIB + t] = g_a[i * DIM + t] + pb1[t];
            sm[OFF_AB2 + t] = ab2[t];
            sm[OFF_PB2 + t] = pb2[t];
        }
    }
    __syncthreads();

    const float2 qv = *(const float2*)(sm + OFF_QI + 2 * lane);
    const u64 pb2p = *(const u64*)(sm + OFF_PB2 + 2 * lane);
    const u64 ab2p = *(const u64*)(sm + OFF_AB2 + 2 * lane);

    float2 Mr = make_float2(-1e30f, -1e30f);
    float2 Lr = make_float2(0.f, 0.f);
    float2 Ar = make_float2(0.f, 0.f);

    for (int j0 = 0; j0 < NTOK; j0 += TJ) {
        // ---- stage 1: PH[r][h] = relu(aib[h] - a_j[h]), warp-private rows ----
        {
            int r = lane >> 2;
            int hb = (lane & 3) * 16;
            const float4* aj = (const float4*)(g_a + (j0 + rw + r) * DIM + hb);
            const float4* aib = (const float4*)(sm + OFF_AIB + hb);
            float4* dst = (float4*)(sm + OFF_HB + (rw + r) * HS + hb);
#pragma unroll
            for (int e = 0; e < 4; e++) {
                float4 av = aj[e];
                float4 bv = aib[e];
                float4 o;
                o.x = fmaxf(bv.x - av.x, 0.f);
                o.y = fmaxf(bv.y - av.y, 0.f);
                o.z = fmaxf(bv.z - av.z, 0.f);
                o.w = fmaxf(bv.w - av.w, 0.f);
                dst[e] = o;
            }
        }
        __syncwarp();

        // ---- stage 2: rpe = PH @ pW2 + pb2 ; U = q - k + rpe ; vv = v + rpe ----
        float2 vvr[RPW];
        {
            u64 racc[RPW];
#pragma unroll
            for (int jj = 0; jj < RPW; jj++) racc[jj] = pb2p;
#pragma unroll 2
            for (int h = 0; h < 64; h += 4) {
                u64 w0 = *(const u64*)(sm + OFF_PW2 + h * 64 + 2 * lane);
                u64 w1 = *(const u64*)(sm + OFF_PW2 + (h + 1) * 64 + 2 * lane);
                u64 w2 = *(const u64*)(sm + OFF_PW2 + (h + 2) * 64 + 2 * lane);
                u64 w3 = *(const u64*)(sm + OFF_PW2 + (h + 3) * 64 + 2 * lane);
#pragma unroll
                for (int jj = 0; jj < RPW; jj++) {
                    float4 ph = *(const float4*)(sm + OFF_HB + (rw + jj) * HS + h);
                    fma2(racc[jj], bcast2(ph.x), w0);
                    fma2(racc[jj], bcast2(ph.y), w1);
                    fma2(racc[jj], bcast2(ph.z), w2);
                    fma2(racc[jj], bcast2(ph.w), w3);
                }
            }
#pragma unroll
            for (int jj = 0; jj < RPW; jj++) {
                int j = j0 + rw + jj;
                float2 rpe = unpack2(racc[jj]);
                float2 kv = *(const float2*)(g_k + j * DIM + 2 * lane);
                float2 vv = *(const float2*)(g_v + j * DIM + 2 * lane);
                float2 uo = make_float2(qv.x - kv.x + rpe.x, qv.y - kv.y + rpe.y);
                vvr[jj] = make_float2(vv.x + rpe.x, vv.y + rpe.y);
                *(float2*)(sm + OFF_U + (rw + jj) * DIM + 2 * lane) = uo;
            }
        }
        __syncwarp();

        // ---- stages 3+4 fused over two 128-col chunks of H_ATTN ----
        u64 acc2[RPW];
#pragma unroll
        for (int jj = 0; jj < RPW; jj++) acc2[jj] = ab2p;

        for (int g = 0; g < 2; g++) {
            // GEMM1 chunk on repacked aW1: acc1[jj][0] = cols (4l,4l+1),
            // acc1[jj][1] = cols (4l+2,4l+3); all weight LDS.64 conflict-free.
            u64 acc1[RPW][2];
            {
                u64 b0 = *(const u64*)(sm + OFF_AB1 + g * 128 + 2 * lane);
                u64 b1 = *(const u64*)(sm + OFF_AB1 + g * 128 + 64 + 2 * lane);
#pragma unroll
                for (int jj = 0; jj < RPW; jj++) { acc1[jj][0] = b0; acc1[jj][1] = b1; }
            }
#pragma unroll 2
            for (int d = 0; d < 64; d += 4) {
                const float* wp = sm + OFF_AW1 + d * 256 + g * 128 + 2 * lane;
                u64 wa0 = *(const u64*)(wp);
                u64 wb0 = *(const u64*)(wp + 64);
                u64 wa1 = *(const u64*)(wp + 256);
                u64 wb1 = *(const u64*)(wp + 320);
                u64 wa2 = *(const u64*)(wp + 512);
                u64 wb2 = *(const u64*)(wp + 576);
                u64 wa3 = *(const u64*)(wp + 768);
                u64 wb3 = *(const u64*)(wp + 832);
#pragma unroll
                for (int jj = 0; jj < RPW; jj++) {
                    float4 u4 = *(const float4*)(sm + OFF_U + (rw + jj) * DIM + d);
                    u64 ux = bcast2(u4.x);
                    u64 uy = bcast2(u4.y);
                    u64 uz = bcast2(u4.z);
                    u64 uw = bcast2(u4.w);
                    fma2(acc1[jj][0], ux, wa0);
                    fma2(acc1[jj][1], ux, wb0);
                    fma2(acc1[jj][0], uy, wa1);
                    fma2(acc1[jj][1], uy, wb1);
                    fma2(acc1[jj][0], uz, wa2);
                    fma2(acc1[jj][1], uz, wb2);
                    fma2(acc1[jj][0], uw, wa3);
                    fma2(acc1[jj][1], uw, wb3);
                }
            }
            __syncwarp();
            // relu + store H chunk (warp-private rows).
            // acc1[jj][0] = H cols (4l,4l+1), acc1[jj][1] = (4l+2,4l+3)
            // -> float4 at column 4*lane, matching GEMM2's row-major H reads.
#pragma unroll
            for (int jj = 0; jj < RPW; jj++) {
                float2 a0 = unpack2(acc1[jj][0]);
                float2 a1 = unpack2(acc1[jj][1]);
                float4 hv;
                hv.x = fmaxf(a0.x, 0.f);
                hv.y = fmaxf(a0.y, 0.f);
                hv.z = fmaxf(a1.x, 0.f);
                hv.w = fmaxf(a1.y, 0.f);
                *(float4*)(sm + OFF_HB + (rw + jj) * HS + 4 * lane) = hv;
            }
            __syncwarp();
            // GEMM2 chunk: acc2 += Hg @ aW2[128g+c, 2lane..2lane+1]
#pragma unroll 2
            for (int c = 0; c < 128; c += 4) {
                const float* wp = sm + OFF_AW2 + (g * 128 + c) * 64 + 2 * lane;
                u64 w0 = *(const u64*)(wp);
                u64 w1 = *(const u64*)(wp + 64);
                u64 w2 = *(const u64*)(wp + 128);
                u64 w3 = *(const u64*)(wp + 192);
#pragma unroll
                for (int jj = 0; jj < RPW; jj++) {
                    float4 hv = *(const float4*)(sm + OFF_HB + (rw + jj) * HS + c);
                    fma2(acc2[jj], bcast2(hv.x), w0);
                    fma2(acc2[jj], bcast2(hv.y), w1);
                    fma2(acc2[jj], bcast2(hv.z), w2);
                    fma2(acc2[jj], bcast2(hv.w), w3);
                }
            }
            __syncwarp();
        }

        // ---- stage 5: per-channel online softmax, all in registers ----
#pragma unroll
        for (int jj = 0; jj < RPW; jj++) {
            float2 s = unpack2(acc2[jj]);
            float mx = fmaxf(Mr.x, s.x);
            float my = fmaxf(Mr.y, s.y);
            float scx = __expf(Mr.x - mx);
            float scy = __expf(Mr.y - my);
            float ex = __expf(s.x - mx);
            float ey = __expf(s.y - my);
            Lr.x = Lr.x * scx + ex;
            Lr.y = Lr.y * scy + ey;
            Ar.x = Ar.x * scx + ex * vvr[jj].x;
            Ar.y = Ar.y * scy + ey * vvr[jj].y;
            Mr.x = mx;
            Mr.y = my;
        }
    }

    // ---- merge per-warp partials ----
    __syncthreads();
    sm[OFF_RED + warp * 64 + 2 * lane] = Mr.x;
    sm[OFF_RED + warp * 64 + 2 * lane + 1] = Mr.y;
    sm[OFF_RED + 512 + warp * 64 + 2 * lane] = Lr.x;
    sm[OFF_RED + 512 + warp * 64 + 2 * lane + 1] = Lr.y;
    sm[OFF_RED + 1024 + warp * 64 + 2 * lane] = Ar.x;
    sm[OFF_RED + 1024 + warp * 64 + 2 * lane + 1] = Ar.y;
    __syncthreads();
    if (t < 64) {
        float M = -1e30f;
#pragma unroll
        for (int w = 0; w < 8; w++) M = fmaxf(M, sm[OFF_RED + w * 64 + t]);
        float L = 0.f, A = 0.f;
#pragma unroll
        for (int w = 0; w < 8; w++) {
            float sc = __expf(sm[OFF_RED + w * 64 + t] - M);
            L += sm[OFF_RED + 512 + w * 64 + t] * sc;
            A += sm[OFF_RED + 1024 + w * 64 + t] * sc;
        }
        out[i * DIM + t] = A / L;
    }
}

extern "C" void kernel_launch(void* const* d_in, const int* in_sizes, int n_in,
                              void* d_out, int out_size) {
    const float* x   = (const float*)d_in[0];
    const float* pos = (const float*)d_in[1];
    const float* Wq  = (const float*)d_in[2];
    const float* Wk  = (const float*)d_in[3];
    const float* Wv  = (const float*)d_in[4];
    const float* pW1 = (const float*)d_in[5];
    const float* pb1 = (const float*)d_in[6];
    const float* pW2 = (const float*)d_in[7];
    const float* pb2 = (const float*)d_in[8];
    const float* aW1 = (const float*)d_in[9];
    const float* ab1 = (const float*)d_in[10];
    const float* aW2 = (const float*)d_in[11];
    const float* ab2 = (const float*)d_in[12];
    float* out = (float*)d_out;

    cudaFuncSetAttribute(pt_main, cudaFuncAttributeMaxDynamicSharedMemorySize, SMEM_BYTES);

    proj_kernel<<<NTOK, DIM>>>(x, pos, Wq, Wk, Wv, pW1);
    pt_main<<<NTOK, 256, SMEM_BYTES>>>(pb1, pW2, pb2, aW1, ab1, aW2, ab2, out);
}